// round 10
// baseline (speedup 1.0000x reference)
#include <cuda_runtime.h>
#include <cuda_fp16.h>
#include <cstdint>
#include <math.h>

// ---- problem constants ----
#define BATCH 4
#define SEQ   1024
#define NE    768
#define DI    1536          // d_inner
#define DS    64            // d_state
#define DTR   4             // dt_rank
#define XDBL  (DTR + 2*DS)  // 132
#define MROWS (BATCH*SEQ)   // 4096

// ---- fp32 scratch ----
__device__ float g_xr   [(size_t)MROWS * 2 * DI];
__device__ float g_xc   [(size_t)MROWS * DI];
__device__ float g_xdbl [(size_t)MROWS * XDBL];
__device__ float g_delta[(size_t)MROWS * DI];

// ---- fp16 GEMM operands ----
__device__ __half g_x_h   [(size_t)MROWS * NE];
__device__ __half g_Win_h [(size_t)2 * DI * NE];
__device__ __half g_xc_h  [(size_t)MROWS * DI];
__device__ __half g_Wx_h  [(size_t)XDBL * DI];
__device__ __half g_u_h   [(size_t)MROWS * DI];
__device__ __half g_Wout_h[(size_t)NE * DI];

// ============================================================
// warp-MMA + cp.async helpers (baseline sm_80+ ISA)
// ============================================================
__device__ __forceinline__ uint32_t smem_u32(const void* p) {
    uint32_t a;
    asm("{ .reg .u64 t; cvta.to.shared.u64 t, %1; cvt.u32.u64 %0, t; }"
        : "=r"(a) : "l"(p));
    return a;
}
__device__ __forceinline__ void ldsm_x4(uint32_t addr, uint32_t r[4]) {
    asm volatile("ldmatrix.sync.aligned.m8n8.x4.shared.b16 {%0,%1,%2,%3}, [%4];"
                 : "=r"(r[0]), "=r"(r[1]), "=r"(r[2]), "=r"(r[3]) : "r"(addr));
}
__device__ __forceinline__ void mma_f16(float c[4], const uint32_t a[4], const uint32_t b[2]) {
    asm volatile(
        "mma.sync.aligned.m16n8k16.row.col.f32.f16.f16.f32 "
        "{%0,%1,%2,%3}, {%4,%5,%6,%7}, {%8,%9}, {%0,%1,%2,%3};"
        : "+f"(c[0]), "+f"(c[1]), "+f"(c[2]), "+f"(c[3])
        : "r"(a[0]), "r"(a[1]), "r"(a[2]), "r"(a[3]), "r"(b[0]), "r"(b[1]));
}
__device__ __forceinline__ void cp16(uint32_t dst, const void* src, uint32_t srcsz) {
    asm volatile("cp.async.cg.shared.global [%0], [%1], 16, %2;"
                 :: "r"(dst), "l"(src), "r"(srcsz));
}
#define CP_COMMIT() asm volatile("cp.async.commit_group;")
#define CP_WAIT1()  asm volatile("cp.async.wait_group 1;")

// ============================================================
// fp16 pipelined HMMA GEMM: C[M,N] = A[M,K] @ B[N,K]^T
// 128x128 CTA tile, BK=64, 2-stage cp.async pipeline,
// 256 threads (8 warps, each 64x32 of C).
// M%128==0, K%64==0 assumed; N guarded.
// ============================================================
#define LDT      72                          // padded row (halves) -> 144B stride (16B-mult)
#define STAGE_A  (128 * LDT * 2)             // 18432 B
#define STAGE_SZ (2 * STAGE_A)               // 36864 B
#define NSTAGE   2
#define G_SMEM   (NSTAGE * STAGE_SZ)         // 73728 B

__global__ __launch_bounds__(256, 2) void gemm_h(
    const __half* __restrict__ A, const __half* __restrict__ B,
    float* __restrict__ C, int M, int N, int K)
{
    extern __shared__ __align__(16) char dsm[];
    const uint32_t sb = smem_u32(dsm);

    const int tid  = threadIdx.x;
    const int wid  = tid >> 5;
    const int lane = tid & 31;
    const int row0 = blockIdx.y * 128;
    const int col0 = blockIdx.x * 128;
    const int wm   = (wid >> 2) * 64;
    const int wn   = (wid & 3) * 32;

    float acc[4][4][4];
    #pragma unroll
    for (int i = 0; i < 4; i++)
        #pragma unroll
        for (int j = 0; j < 4; j++)
            #pragma unroll
            for (int v = 0; v < 4; v++) acc[i][j][v] = 0.f;

    // ldmatrix lane addressing
    const int a_r = lane & 15, a_c = (lane >> 4) << 3;
    const int b_mat = lane >> 3;
    const int b_r = (lane & 7) + ((b_mat >> 1) << 3);
    const int b_c = (b_mat & 1) << 3;

    auto issue = [&](int kc, int st) {
        const int k0 = kc << 6;
        const uint32_t aBase = sb + st * STAGE_SZ;
        const uint32_t bBase = aBase + STAGE_A;
        // 128 rows x 8 16B-segments = 1024 slots per operand; 4 per thread
        #pragma unroll
        for (int i = 0; i < 4; i++) {
            const int s   = tid + (i << 8);       // 0..1023
            const int r   = s >> 3;               // 0..127
            const int c16 = (s & 7) << 3;         // halves: 0,8,...,56
            const uint32_t so = (uint32_t)(r * LDT + c16) * 2;
            cp16(aBase + so, A + (size_t)(row0 + r) * K + k0 + c16, 16);
            const int gn = col0 + r;
            const int gcl = gn < N ? gn : (N - 1);
            cp16(bBase + so, B + (size_t)gcl * K + k0 + c16, gn < N ? 16u : 0u);
        }
        CP_COMMIT();
    };

    const int nch = K >> 6;
    issue(0, 0);

    for (int kc = 0; kc < nch; kc++) {
        if (kc + 1 < nch) issue(kc + 1, (kc + 1) & 1);
        else CP_COMMIT();          // empty group keeps WAIT1 semantics
        CP_WAIT1();
        __syncthreads();

        const uint32_t aBase = sb + (kc & 1) * STAGE_SZ;
        const uint32_t bBase = aBase + STAGE_A;

        #pragma unroll
        for (int ks = 0; ks < 4; ks++) {
            const int kk = ks << 4;
            uint32_t af[4][4];
            #pragma unroll
            for (int mi = 0; mi < 4; mi++)
                ldsm_x4(aBase + (uint32_t)((wm + mi * 16 + a_r) * LDT + kk + a_c) * 2, af[mi]);
            uint32_t bf[4][2];
            #pragma unroll
            for (int np = 0; np < 2; np++) {
                uint32_t r4[4];
                ldsm_x4(bBase + (uint32_t)((wn + np * 16 + b_r) * LDT + kk + b_c) * 2, r4);
                bf[np * 2][0] = r4[0]; bf[np * 2][1] = r4[1];
                bf[np * 2 + 1][0] = r4[2]; bf[np * 2 + 1][1] = r4[3];
            }
            #pragma unroll
            for (int mi = 0; mi < 4; mi++)
                #pragma unroll
                for (int ni = 0; ni < 4; ni++)
                    mma_f16(acc[mi][ni], af[mi], bf[ni]);
        }
        __syncthreads();
    }

    // ---- epilogue ----
    const int groupID = lane >> 2, tig = lane & 3;
    #pragma unroll
    for (int mi = 0; mi < 4; mi++) {
        #pragma unroll
        for (int ni = 0; ni < 4; ni++) {
            int col = col0 + wn + ni * 8 + tig * 2;
            if (col >= N) continue;
            int r0 = row0 + wm + mi * 16 + groupID;
            *(float2*)(C + (size_t)r0 * N + col) =
                make_float2(acc[mi][ni][0], acc[mi][ni][1]);
            *(float2*)(C + (size_t)(r0 + 8) * N + col) =
                make_float2(acc[mi][ni][2], acc[mi][ni][3]);
        }
    }
}

// ============================================================
// fp32 -> fp16 convert
// ============================================================
__global__ __launch_bounds__(256) void cvt_half(
    const float* __restrict__ in, __half* __restrict__ out, int n)
{
    int idx = blockIdx.x * blockDim.x + threadIdx.x;
    if (idx < n) out[idx] = __float2half(in[idx]);
}

// ============================================================
// Depthwise causal conv(4) + bias + SiLU (fp32 + fp16 outs)
// ============================================================
__global__ __launch_bounds__(256) void conv_silu_kernel(
    const float* __restrict__ conv_w, const float* __restrict__ conv_b)
{
    int idx = blockIdx.x * blockDim.x + threadIdx.x;
    if (idx >= MROWS * DI) return;
    int d = idx % DI;
    int m = idx / DI;
    int t = m % SEQ;

    float acc = conv_b[d];
    #pragma unroll
    for (int k = 0; k < 4; k++) {
        int tt = t - 3 + k;
        if (tt >= 0)
            acc = fmaf(conv_w[d * 4 + k],
                       g_xr[(size_t)(m - 3 + k) * (2 * DI) + d], acc);
    }
    float s = acc / (1.f + __expf(-acc));
    g_xc[idx]   = s;
    g_xc_h[idx] = __float2half(s);
}

// ============================================================
// delta = softplus(x_dbl[:, :4] @ W_dt^T + b_dt)
// ============================================================
__global__ __launch_bounds__(256) void delta_kernel(
    const float* __restrict__ W_dt, const float* __restrict__ b_dt)
{
    int idx = blockIdx.x * blockDim.x + threadIdx.x;
    if (idx >= MROWS * DI) return;
    int d = idx % DI;
    int m = idx / DI;
    const float* xd = g_xdbl + (size_t)m * XDBL;
    float z = b_dt[d];
    #pragma unroll
    for (int r = 0; r < DTR; r++)
        z = fmaf(xd[r], W_dt[d * DTR + r], z);
    float sp = (z > 20.f) ? z : log1pf(__expf(z));
    g_delta[idx] = sp;
}

// ============================================================
// Selective scan: one warp per (b, d); each lane owns 2 states.
// Writes u_h = fp16((y + D*x) * silu(res))
// ============================================================
__global__ __launch_bounds__(256) void scan_kernel(
    const float* __restrict__ A_log, const float* __restrict__ Dvec)
{
    const int warpId = threadIdx.x >> 5;
    const int lane   = threadIdx.x & 31;
    const int wg     = blockIdx.x * (blockDim.x >> 5) + warpId;
    if (wg >= BATCH * DI) return;
    const int b = wg / DI;
    const int d = wg % DI;
    const int n0 = 2 * lane;

    const float A0 = -__expf(A_log[d * DS + n0]);
    const float A1 = -__expf(A_log[d * DS + n0 + 1]);
    const float Dd = Dvec[d];

    const float* deltaP = g_delta + (size_t)b * SEQ * DI + d;
    const float* xP     = g_xc    + (size_t)b * SEQ * DI + d;
    const float* resP   = g_xr    + (size_t)b * SEQ * (2 * DI) + DI + d;
    const float* bcP    = g_xdbl  + (size_t)b * SEQ * XDBL;
    __half*      uhP    = g_u_h   + (size_t)b * SEQ * DI + d;

    float h0 = 0.f, h1 = 0.f;

    float  dt_n = deltaP[0];
    float  x_n  = xP[0];
    float  r_n  = resP[0];
    float2 B_n  = *(const float2*)(bcP + DTR + n0);
    float2 C_n  = *(const float2*)(bcP + DTR + DS + n0);

    for (int t = 0; t < SEQ; t++) {
        const float  dt = dt_n, xv = x_n, rv = r_n;
        const float2 Bv = B_n,  Cv = C_n;
        if (t + 1 < SEQ) {
            dt_n = deltaP[(size_t)(t + 1) * DI];
            x_n  = xP[(size_t)(t + 1) * DI];
            r_n  = resP[(size_t)(t + 1) * (2 * DI)];
            B_n  = *(const float2*)(bcP + (size_t)(t + 1) * XDBL + DTR + n0);
            C_n  = *(const float2*)(bcP + (size_t)(t + 1) * XDBL + DTR + DS + n0);
        }

        const float ab0 = __expf(dt * A0);
        const float ab1 = __expf(dt * A1);
        const float dx  = dt * xv;
        h0 = fmaf(ab0, h0, dx * Bv.x);
        h1 = fmaf(ab1, h1, dx * Bv.y);

        float p = fmaf(h0, Cv.x, h1 * Cv.y);
        #pragma unroll
        for (int o = 16; o; o >>= 1)
            p += __shfl_xor_sync(0xffffffffu, p, o);

        if (lane == 0) {
            const float y   = fmaf(Dd, xv, p);
            const float sig = 1.f / (1.f + __expf(-rv));
            uhP[(size_t)t * DI] = __float2half(y * (rv * sig));
        }
    }
}

// ============================================================
// launch  (gemm1 deliberately placed as the 4th launch: the ncu
// capture window grabs launch #4, so next round profiles the GEMM)
// ============================================================
extern "C" void kernel_launch(void* const* d_in, const int* in_sizes, int n_in,
                              void* d_out, int out_size)
{
    const float* x      = (const float*)d_in[0];
    const float* W_in   = (const float*)d_in[1];
    const float* conv_w = (const float*)d_in[2];
    const float* conv_b = (const float*)d_in[3];
    const float* W_x    = (const float*)d_in[4];
    const float* W_dt   = (const float*)d_in[5];
    const float* b_dt   = (const float*)d_in[6];
    const float* A_log  = (const float*)d_in[7];
    const float* Dvec   = (const float*)d_in[8];
    const float* W_out  = (const float*)d_in[9];
    float* out = (float*)d_out;

    static bool attr_done = false;
    if (!attr_done) {
        cudaFuncSetAttribute(gemm_h, cudaFuncAttributeMaxDynamicSharedMemorySize, G_SMEM);
        attr_done = true;
    }

    void *p_xr, *p_xdbl;
    cudaGetSymbolAddress(&p_xr,   g_xr);
    cudaGetSymbolAddress(&p_xdbl, g_xdbl);
    void *p_xh, *p_winh, *p_xch, *p_wxh, *p_uh, *p_woh;
    cudaGetSymbolAddress(&p_xh,   g_x_h);
    cudaGetSymbolAddress(&p_winh, g_Win_h);
    cudaGetSymbolAddress(&p_xch,  g_xc_h);
    cudaGetSymbolAddress(&p_wxh,  g_Wx_h);
    cudaGetSymbolAddress(&p_uh,   g_u_h);
    cudaGetSymbolAddress(&p_woh,  g_Wout_h);

    // #1-#3: converts needed before gemm1 / gemm2
    {
        int n = MROWS * NE;
        cvt_half<<<(n + 255) / 256, 256>>>(x, (__half*)p_xh, n);
        n = 2 * DI * NE;
        cvt_half<<<(n + 255) / 256, 256>>>(W_in, (__half*)p_winh, n);
        n = XDBL * DI;
        cvt_half<<<(n + 255) / 256, 256>>>(W_x, (__half*)p_wxh, n);
    }
    // #4: xr = x @ W_in^T : [4096, 3072], K=768   <-- profiled launch
    {
        dim3 grid((2 * DI) / 128, MROWS / 128);
        gemm_h<<<grid, 256, G_SMEM>>>((const __half*)p_xh, (const __half*)p_winh,
                                      (float*)p_xr, MROWS, 2 * DI, NE);
    }
    // #5: conv + silu
    {
        int n = MROWS * DI;
        conv_silu_kernel<<<(n + 255) / 256, 256>>>(conv_w, conv_b);
    }
    // #6: x_dbl = x_ssm @ W_x^T : [4096, 132], K=1536
    {
        dim3 grid((XDBL + 127) / 128, MROWS / 128);
        gemm_h<<<grid, 256, G_SMEM>>>((const __half*)p_xch, (const __half*)p_wxh,
                                      (float*)p_xdbl, MROWS, XDBL, DI);
    }
    // #7: delta
    {
        int n = MROWS * DI;
        delta_kernel<<<(n + 255) / 256, 256>>>(W_dt, b_dt);
    }
    // #8: selective scan -> u_h
    {
        int nwarps = BATCH * DI;
        int wpb = 8;
        scan_kernel<<<(nwarps + wpb - 1) / wpb, wpb * 32>>>(A_log, Dvec);
    }
    // #9: convert W_out (only needed by gemm3)
    {
        int n = NE * DI;
        cvt_half<<<(n + 255) / 256, 256>>>(W_out, (__half*)p_woh, n);
    }
    // #10: out = u @ W_out^T : [4096, 768], K=1536
    {
        dim3 grid(NE / 128, MROWS / 128);
        gemm_h<<<grid, 256, G_SMEM>>>((const __half*)p_uh, (const __half*)p_woh,
                                      out, MROWS, NE, DI);
    }
}

// round 13
// speedup vs baseline: 1.9792x; 1.9792x over previous
#include <cuda_runtime.h>
#include <cuda_fp16.h>
#include <cstdint>
#include <math.h>

// ---- problem constants ----
#define BATCH 4
#define SEQ   1024
#define NE    768
#define DI    1536          // d_inner
#define DS    64            // d_state
#define DTR   4             // dt_rank
#define XDBL  (DTR + 2*DS)  // 132
#define MROWS (BATCH*SEQ)   // 4096

// ---- fp32 scratch ----
__device__ float g_xr   [(size_t)MROWS * 2 * DI];
__device__ float g_xc   [(size_t)MROWS * DI];
__device__ float g_xdbl [(size_t)MROWS * XDBL];

// ---- fp16 GEMM operands ----
__device__ __half g_x_h   [(size_t)MROWS * NE];
__device__ __half g_Win_h [(size_t)2 * DI * NE];
__device__ __half g_xc_h  [(size_t)MROWS * DI];
__device__ __half g_Wx_h  [(size_t)XDBL * DI];
__device__ __half g_u_h   [(size_t)MROWS * DI];
__device__ __half g_Wout_h[(size_t)NE * DI];

// ============================================================
// warp-MMA + cp.async helpers (baseline sm_80+ ISA)
// ============================================================
__device__ __forceinline__ uint32_t smem_u32(const void* p) {
    uint32_t a;
    asm("{ .reg .u64 t; cvta.to.shared.u64 t, %1; cvt.u32.u64 %0, t; }"
        : "=r"(a) : "l"(p));
    return a;
}
__device__ __forceinline__ void ldsm_x4(uint32_t addr, uint32_t r[4]) {
    asm volatile("ldmatrix.sync.aligned.m8n8.x4.shared.b16 {%0,%1,%2,%3}, [%4];"
                 : "=r"(r[0]), "=r"(r[1]), "=r"(r[2]), "=r"(r[3]) : "r"(addr));
}
__device__ __forceinline__ void mma_f16(float c[4], const uint32_t a[4], const uint32_t b[2]) {
    asm volatile(
        "mma.sync.aligned.m16n8k16.row.col.f32.f16.f16.f32 "
        "{%0,%1,%2,%3}, {%4,%5,%6,%7}, {%8,%9}, {%0,%1,%2,%3};"
        : "+f"(c[0]), "+f"(c[1]), "+f"(c[2]), "+f"(c[3])
        : "r"(a[0]), "r"(a[1]), "r"(a[2]), "r"(a[3]), "r"(b[0]), "r"(b[1]));
}
__device__ __forceinline__ void cp16(uint32_t dst, const void* src, uint32_t srcsz) {
    asm volatile("cp.async.cg.shared.global [%0], [%1], 16, %2;"
                 :: "r"(dst), "l"(src), "r"(srcsz));
}
#define CP_COMMIT() asm volatile("cp.async.commit_group;")
#define CP_WAIT1()  asm volatile("cp.async.wait_group 1;")

// ============================================================
// fp16 pipelined HMMA GEMM: C[M,N] = A[M,K] @ B[N,K]^T
// 128x128 CTA tile, BK=64, 2-stage cp.async pipeline, 256 thr.
// ============================================================
#define LDT      72
#define STAGE_A  (128 * LDT * 2)
#define STAGE_SZ (2 * STAGE_A)
#define G_SMEM   (2 * STAGE_SZ)              // 73728 B

__global__ __launch_bounds__(256, 2) void gemm_h(
    const __half* __restrict__ A, const __half* __restrict__ B,
    float* __restrict__ C, int M, int N, int K)
{
    extern __shared__ __align__(16) char dsm[];
    const uint32_t sb = smem_u32(dsm);

    const int tid  = threadIdx.x;
    const int wid  = tid >> 5;
    const int lane = tid & 31;
    const int row0 = blockIdx.y * 128;
    const int col0 = blockIdx.x * 128;
    const int wm   = (wid >> 2) * 64;
    const int wn   = (wid & 3) * 32;

    float acc[4][4][4];
    #pragma unroll
    for (int i = 0; i < 4; i++)
        #pragma unroll
        for (int j = 0; j < 4; j++)
            #pragma unroll
            for (int v = 0; v < 4; v++) acc[i][j][v] = 0.f;

    const int a_r = lane & 15, a_c = (lane >> 4) << 3;
    const int b_mat = lane >> 3;
    const int b_r = (lane & 7) + ((b_mat >> 1) << 3);
    const int b_c = (b_mat & 1) << 3;

    auto issue = [&](int kc, int st) {
        const int k0 = kc << 6;
        const uint32_t aBase = sb + st * STAGE_SZ;
        const uint32_t bBase = aBase + STAGE_A;
        #pragma unroll
        for (int i = 0; i < 4; i++) {
            const int s   = tid + (i << 8);
            const int r   = s >> 3;
            const int c16 = (s & 7) << 3;
            const uint32_t so = (uint32_t)(r * LDT + c16) * 2;
            cp16(aBase + so, A + (size_t)(row0 + r) * K + k0 + c16, 16);
            const int gn = col0 + r;
            const int gcl = gn < N ? gn : (N - 1);
            cp16(bBase + so, B + (size_t)gcl * K + k0 + c16, gn < N ? 16u : 0u);
        }
        CP_COMMIT();
    };

    const int nch = K >> 6;
    issue(0, 0);

    for (int kc = 0; kc < nch; kc++) {
        if (kc + 1 < nch) issue(kc + 1, (kc + 1) & 1);
        else CP_COMMIT();
        CP_WAIT1();
        __syncthreads();

        const uint32_t aBase = sb + (kc & 1) * STAGE_SZ;
        const uint32_t bBase = aBase + STAGE_A;

        #pragma unroll
        for (int ks = 0; ks < 4; ks++) {
            const int kk = ks << 4;
            uint32_t af[4][4];
            #pragma unroll
            for (int mi = 0; mi < 4; mi++)
                ldsm_x4(aBase + (uint32_t)((wm + mi * 16 + a_r) * LDT + kk + a_c) * 2, af[mi]);
            uint32_t bf[4][2];
            #pragma unroll
            for (int np = 0; np < 2; np++) {
                uint32_t r4[4];
                ldsm_x4(bBase + (uint32_t)((wn + np * 16 + b_r) * LDT + kk + b_c) * 2, r4);
                bf[np * 2][0] = r4[0]; bf[np * 2][1] = r4[1];
                bf[np * 2 + 1][0] = r4[2]; bf[np * 2 + 1][1] = r4[3];
            }
            #pragma unroll
            for (int mi = 0; mi < 4; mi++)
                #pragma unroll
                for (int ni = 0; ni < 4; ni++)
                    mma_f16(acc[mi][ni], af[mi], bf[ni]);
        }
        __syncthreads();
    }

    const int groupID = lane >> 2, tig = lane & 3;
    #pragma unroll
    for (int mi = 0; mi < 4; mi++) {
        #pragma unroll
        for (int ni = 0; ni < 4; ni++) {
            int col = col0 + wn + ni * 8 + tig * 2;
            if (col >= N) continue;
            int r0 = row0 + wm + mi * 16 + groupID;
            *(float2*)(C + (size_t)r0 * N + col) =
                make_float2(acc[mi][ni][0], acc[mi][ni][1]);
            *(float2*)(C + (size_t)(r0 + 8) * N + col) =
                make_float2(acc[mi][ni][2], acc[mi][ni][3]);
        }
    }
}

// ============================================================
// fused fp32->fp16 convert of all 4 GEMM operands (1 launch)
// ============================================================
#define CVT_N0 (MROWS * NE)
#define CVT_N1 (2 * DI * NE)
#define CVT_N2 (XDBL * DI)
#define CVT_N3 (NE * DI)
#define CVT_TOT (CVT_N0 + CVT_N1 + CVT_N2 + CVT_N3)

__global__ __launch_bounds__(256) void cvt_all(
    const float* __restrict__ x, const float* __restrict__ Win,
    const float* __restrict__ Wx, const float* __restrict__ Wout)
{
    int idx = blockIdx.x * blockDim.x + threadIdx.x;
    if (idx < CVT_N0) { g_x_h[idx] = __float2half(x[idx]); return; }
    idx -= CVT_N0;
    if (idx < CVT_N1) { g_Win_h[idx] = __float2half(Win[idx]); return; }
    idx -= CVT_N1;
    if (idx < CVT_N2) { g_Wx_h[idx] = __float2half(Wx[idx]); return; }
    idx -= CVT_N2;
    if (idx < CVT_N3) { g_Wout_h[idx] = __float2half(Wout[idx]); }
}

// ============================================================
// Depthwise causal conv(4) + bias + SiLU (fp32 + fp16 outs)
// ============================================================
__global__ __launch_bounds__(256) void conv_silu_kernel(
    const float* __restrict__ conv_w, const float* __restrict__ conv_b)
{
    int idx = blockIdx.x * blockDim.x + threadIdx.x;
    if (idx >= MROWS * DI) return;
    int d = idx % DI;
    int m = idx / DI;
    int t = m % SEQ;

    float acc = conv_b[d];
    #pragma unroll
    for (int k = 0; k < 4; k++) {
        int tt = t - 3 + k;
        if (tt >= 0)
            acc = fmaf(conv_w[d * 4 + k],
                       g_xr[(size_t)(m - 3 + k) * (2 * DI) + d], acc);
    }
    float s = acc / (1.f + __expf(-acc));
    g_xc[idx]   = s;
    g_xc_h[idx] = __float2half(s);
}

// ============================================================
// Selective scan, restructured:
//  - one warp per (b,d); lane owns 2 states
//  - delta (softplus) fused, computed 32-t at a time (lane j -> t_j)
//  - per-t partials go to transposed smem tile; reduction + epilogue
//    done once per 32-t group, one t per lane (no shuffles)
// ============================================================
#define WPB 8
__global__ __launch_bounds__(WPB * 32) void scan_kernel(
    const float* __restrict__ A_log, const float* __restrict__ Dvec,
    const float* __restrict__ W_dt, const float* __restrict__ b_dt)
{
    __shared__ float p_s [WPB][32][33];
    __shared__ float dt_s[WPB][32];
    __shared__ float x_s [WPB][32];

    const int w    = threadIdx.x >> 5;
    const int lane = threadIdx.x & 31;
    const int wg   = blockIdx.x * WPB + w;
    const int b = wg / DI;
    const int d = wg % DI;
    const int n0 = 2 * lane;

    const float LOG2E = 1.4426950408889634f;
    const float A0L = -__expf(A_log[d * DS + n0])     * LOG2E;
    const float A1L = -__expf(A_log[d * DS + n0 + 1]) * LOG2E;
    const float Dd  = Dvec[d];
    const float4 wdt = *(const float4*)(W_dt + d * 4);
    const float bdt = b_dt[d];

    const float* bcP  = g_xdbl + (size_t)b * SEQ * XDBL;
    const float* xP   = g_xc   + (size_t)b * SEQ * DI + d;
    const float* resP = g_xr   + (size_t)b * SEQ * (2 * DI) + DI + d;
    __half*      uhP  = g_u_h  + (size_t)b * SEQ * DI + d;

    float h0 = 0.f, h1 = 0.f;

    // prefetch B/C for t=0
    float2 Bn = *(const float2*)(bcP + DTR + n0);
    float2 Cn = *(const float2*)(bcP + DTR + DS + n0);

    for (int g = 0; g < SEQ / 32; g++) {
        const int t_j = g * 32 + lane;   // this lane's timestep for A/C phases

        // --- phase A: delta + x for the 32 timesteps of this group ---
        const float4 xd = *(const float4*)(bcP + (size_t)t_j * XDBL);
        float z = bdt;
        z = fmaf(xd.x, wdt.x, z);
        z = fmaf(xd.y, wdt.y, z);
        z = fmaf(xd.z, wdt.z, z);
        z = fmaf(xd.w, wdt.w, z);
        dt_s[w][lane] = (z > 20.f) ? z : log1pf(__expf(z));
        x_s[w][lane]  = xP[(size_t)t_j * DI];
        __syncwarp();

        // --- phase B: serial scan over the 32 steps ---
        #pragma unroll 4
        for (int j = 0; j < 32; j++) {
            const int t = g * 32 + j;
            const float dt = dt_s[w][j];
            const float xv = x_s[w][j];
            const float2 Bv = Bn, Cv = Cn;
            if (t + 1 < SEQ) {
                Bn = *(const float2*)(bcP + (size_t)(t + 1) * XDBL + DTR + n0);
                Cn = *(const float2*)(bcP + (size_t)(t + 1) * XDBL + DTR + DS + n0);
            }
            const float ab0 = exp2f(dt * A0L);
            const float ab1 = exp2f(dt * A1L);
            const float dx  = dt * xv;
            h0 = fmaf(ab0, h0, dx * Bv.x);
            h1 = fmaf(ab1, h1, dx * Bv.y);
            p_s[w][j][lane] = fmaf(h0, Cv.x, h1 * Cv.y);
        }
        __syncwarp();

        // --- phase C: reduction + epilogue, one t per lane ---
        float s0 = 0.f, s1 = 0.f;
        #pragma unroll
        for (int i = 0; i < 32; i += 2) {
            s0 += p_s[w][lane][i];
            s1 += p_s[w][lane][i + 1];
        }
        const float y  = fmaf(Dd, x_s[w][lane], s0 + s1);
        const float rv = resP[(size_t)t_j * (2 * DI)];
        const float sig = 1.f / (1.f + __expf(-rv));
        uhP[(size_t)t_j * DI] = __float2half(y * (rv * sig));
        __syncwarp();
    }
}

// ============================================================
// launch
// order: cvt_all(1), gemm1(2), conv(3), gemm2(4=profiled),
//        scan(5), gemm3(6)
// ============================================================
extern "C" void kernel_launch(void* const* d_in, const int* in_sizes, int n_in,
                              void* d_out, int out_size)
{
    const float* x      = (const float*)d_in[0];
    const float* W_in   = (const float*)d_in[1];
    const float* conv_w = (const float*)d_in[2];
    const float* conv_b = (const float*)d_in[3];
    const float* W_x    = (const float*)d_in[4];
    const float* W_dt   = (const float*)d_in[5];
    const float* b_dt   = (const float*)d_in[6];
    const float* A_log  = (const float*)d_in[7];
    const float* Dvec   = (const float*)d_in[8];
    const float* W_out  = (const float*)d_in[9];
    float* out = (float*)d_out;

    static bool attr_done = false;
    if (!attr_done) {
        cudaFuncSetAttribute(gemm_h, cudaFuncAttributeMaxDynamicSharedMemorySize, G_SMEM);
        attr_done = true;
    }

    void *p_xr, *p_xdbl;
    cudaGetSymbolAddress(&p_xr,   g_xr);
    cudaGetSymbolAddress(&p_xdbl, g_xdbl);
    void *p_xh, *p_winh, *p_xch, *p_wxh, *p_uh, *p_woh;
    cudaGetSymbolAddress(&p_xh,   g_x_h);
    cudaGetSymbolAddress(&p_winh, g_Win_h);
    cudaGetSymbolAddress(&p_xch,  g_xc_h);
    cudaGetSymbolAddress(&p_wxh,  g_Wx_h);
    cudaGetSymbolAddress(&p_uh,   g_u_h);
    cudaGetSymbolAddress(&p_woh,  g_Wout_h);

    // #1: all fp16 converts in one launch
    cvt_all<<<(CVT_TOT + 255) / 256, 256>>>(x, W_in, W_x, W_out);

    // #2: xr = x @ W_in^T : [4096, 3072], K=768
    {
        dim3 grid((2 * DI) / 128, MROWS / 128);
        gemm_h<<<grid, 256, G_SMEM>>>((const __half*)p_xh, (const __half*)p_winh,
                                      (float*)p_xr, MROWS, 2 * DI, NE);
    }
    // #3: conv + silu
    {
        int n = MROWS * DI;
        conv_silu_kernel<<<(n + 255) / 256, 256>>>(conv_w, conv_b);
    }
    // #4: x_dbl = x_ssm @ W_x^T : [4096, 132], K=1536   <-- profiled
    {
        dim3 grid((XDBL + 127) / 128, MROWS / 128);
        gemm_h<<<grid, 256, G_SMEM>>>((const __half*)p_xch, (const __half*)p_wxh,
                                      (float*)p_xdbl, MROWS, XDBL, DI);
    }
    // #5: selective scan (delta fused) -> u_h
    {
        int nwarps = BATCH * DI;                 // 6144
        scan_kernel<<<nwarps / WPB, WPB * 32>>>(A_log, Dvec, W_dt, b_dt);
    }
    // #6: out = u @ W_out^T : [4096, 768], K=1536
    {
        dim3 grid(NE / 128, MROWS / 128);
        gemm_h<<<grid, 256, G_SMEM>>>((const __half*)p_uh, (const __half*)p_woh,
                                      out, MROWS, NE, DI);
    }
}